// round 13
// baseline (speedup 1.0000x reference)
#include <cuda_runtime.h>
#include <math.h>

#define NROW 16384          // B*F rows
#define MTOT 65536          // NPRED * NROW

// Scratch (static device arrays — allocation-free)
__device__ float g_z[NROW * 15 * 128];   // window embeddings z_0..z_14 per row
__device__ float g_zn2[NROW * 15];       // squared norms of z
__device__ float g_t0[MTOT * 128];       // logmap0(z_next) per (iter,row)
__device__ float g_w1dup[128 * 512 * 2]; // W1 with every value duplicated (packed pairs)

// ---------------------------------------------------------------- helpers
__device__ __forceinline__ float wsum(float v) {
#pragma unroll
    for (int o = 16; o; o >>= 1) v += __shfl_xor_sync(0xffffffffu, v, o);
    return v;
}
__device__ __forceinline__ float artanh_c(float x) {
    x = fminf(fmaxf(x, -1.0f + 1e-7f), 1.0f - 1e-7f);
    return 0.5f * logf((1.0f + x) / (1.0f - x));
}
typedef unsigned long long ull;
__device__ __forceinline__ void fma2(ull& c, ull a, ull b) {
    asm("fma.rn.f32x2 %0, %1, %2, %0;" : "+l"(c) : "l"(a), "l"(b));
}
__device__ __forceinline__ ull splat2(float x) {
    ull r; asm("mov.b64 %0, {%1, %1};" : "=l"(r) : "f"(x)); return r;
}
__device__ __forceinline__ void unpack2(ull v, float& lo, float& hi) {
    asm("mov.b64 {%0, %1}, %2;" : "=f"(lo), "=f"(hi) : "l"(v));
}
// 16B shared load delivering two packed f32 pairs (no movs)
__device__ __forceinline__ void lds2u(ull& a, ull& b, const float* p) {
    unsigned sa = (unsigned)__cvta_generic_to_shared(p);
    asm("ld.shared.v2.b64 {%0,%1}, [%2];" : "=l"(a), "=l"(b) : "r"(sa));
}
// 16B global load delivering two packed f32 pairs (no movs)
__device__ __forceinline__ void ldg2u(ull& a, ull& b, const float* p) {
    asm("ld.global.nc.v2.u64 {%0,%1}, [%2];" : "=l"(a), "=l"(b) : "l"(p));
}

// logmap(x, y) -> velocity vector (lane holds 4 of 128 dims); serial version
__device__ __forceinline__ void logmap_v(float4 x4, float x2, float4 y4, float y2,
                                         float& v0, float& v1, float& v2, float& v3)
{
    float xy = wsum(x4.x*y4.x + x4.y*y4.y + x4.z*y4.z + x4.w*y4.w);
    float cA = 1.0f - 2.0f*xy + y2;
    float cB = 1.0f - x2;
    float iden = 1.0f / fmaxf(1.0f - 2.0f*xy + x2*y2, 1e-6f);
    float d0 = (cB*y4.x - cA*x4.x)*iden;
    float d1 = (cB*y4.y - cA*x4.y)*iden;
    float d2 = (cB*y4.z - cA*x4.z)*iden;
    float d3 = (cB*y4.w - cA*x4.w)*iden;
    float n2 = wsum(d0*d0 + d1*d1 + d2*d2 + d3*d3);
    float n  = sqrtf(fmaxf(n2, 1e-12f));
    float fac = fmaxf(cB, 1e-6f) * artanh_c(n) / n;
    v0 = fac*d0; v1 = fac*d1; v2 = fac*d2; v3 = fac*d3;
}

// ---------------------------------------------------------------------------
// KPREP: duplicate W1 values into packed-pair layout g_w1dup[k*1024 + c*2 + e]
// ---------------------------------------------------------------------------
__global__ void kprep_kernel(const float* __restrict__ W1)
{
    int i = blockIdx.x * 256 + threadIdx.x;      // 0..65535 over k*512+c
    float v = W1[i];
    g_w1dup[i * 2]     = v;
    g_w1dup[i * 2 + 1] = v;
}

// ---------------------------------------------------------------------------
// KA1: embedding GEMM + expmap0.  Block = (b, segment j of window).
// Warp = 16 f rows (8 packed f-pairs), lane = 4 dims.
// Mainloop software-pipelined: weights for k+1 prefetched before the FMA body.
// ---------------------------------------------------------------------------
__global__ __launch_bounds__(256, 2)
void ka1_kernel(const float* __restrict__ trend, const float* __restrict__ scoar,
                const float* __restrict__ sfin,  const float* __restrict__ resid,
                const float* __restrict__ Wt, const float* __restrict__ bt,
                const float* __restrict__ Wc, const float* __restrict__ bc,
                const float* __restrict__ Wf, const float* __restrict__ bff,
                const float* __restrict__ Wr, const float* __restrict__ br)
{
    extern __shared__ float sm[];
    float* sA    = sm;            // [96 k][128 f]
    float* sW    = sA + 12288;    // [96 k][128 d]
    float* sbias = sW + 12288;    // 128

    const int tid = threadIdx.x;
    const int b = blockIdx.x / 15;
    const int j = blockIdx.x - b * 15;
    const int lbase = b * 720 + 360 + j * 24;

    {
        const float* ptrs[4] = {trend, scoar, sfin, resid};
        const float* wptr[4] = {Wt, Wc, Wf, Wr};
#pragma unroll
        for (int st = 0; st < 4; ++st) {
            const float* p = ptrs[st] + lbase * 128;
            for (int idx = tid; idx < 3072; idx += 256) sA[st * 3072 + idx] = p[idx];
            const float* wp = wptr[st];
            for (int idx = tid; idx < 3072; idx += 256) sW[st * 3072 + idx] = wp[idx];
        }
    }
    if (tid < 128) sbias[tid] = bt[tid] + bc[tid] + bff[tid] + br[tid];
    __syncthreads();

    const int w = tid >> 5, lane = tid & 31;
    const int fb = w * 16;

    const float4 bias4 = ((const float4*)sbias)[lane];
    ull bini[4] = { splat2(bias4.x), splat2(bias4.y), splat2(bias4.z), splat2(bias4.w) };
    ull acc[8][4];
#pragma unroll
    for (int p = 0; p < 8; ++p)
#pragma unroll
        for (int d = 0; d < 4; ++d) acc[p][d] = bini[d];

    const float4* sW4 = (const float4*)sW;
    float4 wvp = sW4[lane];                       // prefetch k=0 weights
#pragma unroll 2
    for (int k = 0; k < 96; ++k) {
        float4 wv = wvp;
        if (k < 95) wvp = sW4[(k + 1) * 32 + lane];   // prefetch next k
        ull wd0 = splat2(wv.x), wd1 = splat2(wv.y), wd2 = splat2(wv.z), wd3 = splat2(wv.w);
        const float* ab = sA + k * 128 + fb;      // f-contiguous (broadcast)
        ull a0, a1, a2, a3, a4, a5, a6, a7;
        lds2u(a0, a1, ab);
        lds2u(a2, a3, ab + 4);
        lds2u(a4, a5, ab + 8);
        lds2u(a6, a7, ab + 12);
        fma2(acc[0][0], a0, wd0); fma2(acc[0][1], a0, wd1); fma2(acc[0][2], a0, wd2); fma2(acc[0][3], a0, wd3);
        fma2(acc[1][0], a1, wd0); fma2(acc[1][1], a1, wd1); fma2(acc[1][2], a1, wd2); fma2(acc[1][3], a1, wd3);
        fma2(acc[2][0], a2, wd0); fma2(acc[2][1], a2, wd1); fma2(acc[2][2], a2, wd2); fma2(acc[2][3], a2, wd3);
        fma2(acc[3][0], a3, wd0); fma2(acc[3][1], a3, wd1); fma2(acc[3][2], a3, wd2); fma2(acc[3][3], a3, wd3);
        fma2(acc[4][0], a4, wd0); fma2(acc[4][1], a4, wd1); fma2(acc[4][2], a4, wd2); fma2(acc[4][3], a4, wd3);
        fma2(acc[5][0], a5, wd0); fma2(acc[5][1], a5, wd1); fma2(acc[5][2], a5, wd2); fma2(acc[5][3], a5, wd3);
        fma2(acc[6][0], a6, wd0); fma2(acc[6][1], a6, wd1); fma2(acc[6][2], a6, wd2); fma2(acc[6][3], a6, wd3);
        fma2(acc[7][0], a7, wd0); fma2(acc[7][1], a7, wd1); fma2(acc[7][2], a7, wd2); fma2(acc[7][3], a7, wd3);
    }

    // ---- epilogue: batched reductions over 16 rows ----
    float pn[16];
#pragma unroll
    for (int p = 0; p < 8; ++p) {
        float lo0, hi0, lo1, hi1, lo2, hi2, lo3, hi3;
        unpack2(acc[p][0], lo0, hi0);
        unpack2(acc[p][1], lo1, hi1);
        unpack2(acc[p][2], lo2, hi2);
        unpack2(acc[p][3], lo3, hi3);
        pn[2*p]   = lo0*lo0 + lo1*lo1 + lo2*lo2 + lo3*lo3;
        pn[2*p+1] = hi0*hi0 + hi1*hi1 + hi2*hi2 + hi3*hi3;
    }
#pragma unroll
    for (int o = 16; o; o >>= 1)
#pragma unroll
        for (int r = 0; r < 16; ++r)
            pn[r] += __shfl_xor_sync(0xffffffffu, pn[r], o);

    const int rowb = b * 128 + fb;
#pragma unroll
    for (int p = 0; p < 8; ++p) {
        float v[2][4];
        unpack2(acc[p][0], v[0][0], v[1][0]);
        unpack2(acc[p][1], v[0][1], v[1][1]);
        unpack2(acc[p][2], v[0][2], v[1][2]);
        unpack2(acc[p][3], v[0][3], v[1][3]);
#pragma unroll
        for (int e = 0; e < 2; ++e) {
            float n2 = pn[2*p + e];
            float n  = sqrtf(fmaxf(n2, 1e-12f));
            float t  = tanhf(n);
            float tc = fminf(t, 0.99999f);     // |z| = tanh(n); project clamps it
            float scl = tc / n;
            int row = rowb + 2 * p + e;
            ((float4*)(g_z + (row * 15 + j) * 128))[lane] =
                make_float4(scl*v[e][0], scl*v[e][1], scl*v[e][2], scl*v[e][3]);
            if (lane == 0) g_zn2[row * 15 + j] = tc * tc;
        }
    }
}

// ---------------------------------------------------------------------------
// KA2: 4-step recurrence.  Warp = one (b,f) row; lane = 4 dims.
// (unchanged from R9)
// ---------------------------------------------------------------------------
__global__ __launch_bounds__(256)
void ka2_kernel(const float* __restrict__ alphap)
{
    const int w = threadIdx.x >> 5, lane = threadIdx.x & 31;
    const int row = blockIdx.x * 8 + w;
    const float alpha = alphap[0];

    float S = 0.0f, p = 1.0f;
#pragma unroll
    for (int e = 0; e < 14; ++e) { S += p; p *= 0.9f; }
    const float w13 = 1.0f / S;
    float w0 = w13;
#pragma unroll
    for (int e = 0; e < 13; ++e) w0 *= 0.9f;
    const float inv09 = 1.0f / 0.9f;

    const float* zp = g_z   + row * 15 * 128;
    const float* np = g_zn2 + row * 15;

    float4 z[15]; float zn[15];
#pragma unroll
    for (int jj = 0; jj < 15; ++jj) {
        z[jj]  = ((const float4*)(zp + jj * 128))[lane];
        zn[jj] = __ldg(np + jj);
    }

    float px[14];
#pragma unroll
    for (int jj = 0; jj < 14; ++jj)
        px[jj] = z[jj].x*z[jj+1].x + z[jj].y*z[jj+1].y +
                 z[jj].z*z[jj+1].z + z[jj].w*z[jj+1].w;
#pragma unroll
    for (int o = 16; o; o >>= 1)
#pragma unroll
        for (int jj = 0; jj < 14; ++jj)
            px[jj] += __shfl_xor_sync(0xffffffffu, px[jj], o);

    float d[14][4]; float pn[14];
#pragma unroll
    for (int jj = 0; jj < 14; ++jj) {
        float x2 = zn[jj], y2 = zn[jj+1], xy = px[jj];
        float cA = 1.0f - 2.0f*xy + y2;
        float cB = 1.0f - x2;
        float iden = 1.0f / fmaxf(1.0f - 2.0f*xy + x2*y2, 1e-6f);
        d[jj][0] = (cB*z[jj+1].x - cA*z[jj].x)*iden;
        d[jj][1] = (cB*z[jj+1].y - cA*z[jj].y)*iden;
        d[jj][2] = (cB*z[jj+1].z - cA*z[jj].z)*iden;
        d[jj][3] = (cB*z[jj+1].w - cA*z[jj].w)*iden;
        pn[jj] = d[jj][0]*d[jj][0] + d[jj][1]*d[jj][1] +
                 d[jj][2]*d[jj][2] + d[jj][3]*d[jj][3];
    }
#pragma unroll
    for (int o = 16; o; o >>= 1)
#pragma unroll
        for (int jj = 0; jj < 14; ++jj)
            pn[jj] += __shfl_xor_sync(0xffffffffu, pn[jj], o);

    float av0 = 0.f, av1 = 0.f, av2 = 0.f, av3 = 0.f;
    float vc[3][4];
    float wcur = w0;
#pragma unroll
    for (int jj = 0; jj < 14; ++jj) {
        float n = sqrtf(fmaxf(pn[jj], 1e-12f));
        float fac = fmaxf(1.0f - zn[jj], 1e-6f) * artanh_c(n) / n;
        float v0 = fac*d[jj][0], v1 = fac*d[jj][1], v2 = fac*d[jj][2], v3 = fac*d[jj][3];
        if (jj < 3) { vc[jj][0] = v0; vc[jj][1] = v1; vc[jj][2] = v2; vc[jj][3] = v3; }
        av0 = fmaf(wcur, v0, av0); av1 = fmaf(wcur, v1, av1);
        av2 = fmaf(wcur, v2, av2); av3 = fmaf(wcur, v3, av3);
        wcur *= inv09;
    }

    float4 x4 = z[14];
    float  x2 = zn[14];

#pragma unroll
    for (int i = 0; i < 4; ++i) {
        float v0 = alpha * av0, v1 = alpha * av1, v2 = alpha * av2, v3 = alpha * av3;
        float nv2 = wsum(v0*v0 + v1*v1 + v2*v2 + v3*v3);
        float nv  = sqrtf(fmaxf(nv2, 1e-12f));
        float om  = fmaxf(1.0f - x2, 1e-6f);
        float sscl = tanhf(nv / om) / nv;
        float e0 = sscl*v0, e1 = sscl*v1, e2 = sscl*v2, e3 = sscl*v3;
        float xy = wsum(x4.x*e0 + x4.y*e1 + x4.z*e2 + x4.w*e3);
        float s2 = wsum(e0*e0 + e1*e1 + e2*e2 + e3*e3);
        float cA = 1.0f + 2.0f*xy + s2;
        float cB = 1.0f - x2;
        float iden = 1.0f / fmaxf(1.0f + 2.0f*xy + x2*s2, 1e-6f);
        float z0 = (cA*x4.x + cB*e0)*iden;
        float z1 = (cA*x4.y + cB*e1)*iden;
        float z2 = (cA*x4.z + cB*e2)*iden;
        float z3 = (cA*x4.w + cB*e3)*iden;
        float zn2 = wsum(z0*z0 + z1*z1 + z2*z2 + z3*z3);
        float znn = sqrtf(fmaxf(zn2, 1e-12f));
        if (znn > 0.99999f) {
            float ps = 0.99999f / znn;
            z0 *= ps; z1 *= ps; z2 *= ps; z3 *= ps;
            zn2 *= ps * ps;
        }
        float tn = sqrtf(fmaxf(zn2, 1e-12f));
        float tf = artanh_c(tn) / tn;
        ((float4*)(g_t0 + (i * NROW + row) * 128))[lane] =
            make_float4(tf*z0, tf*z1, tf*z2, tf*z3);

        if (i < 3) {
            float4 zn4 = make_float4(z0, z1, z2, z3);
            float nv0, nv1, nv2b, nv3;
            logmap_v(x4, x2, zn4, zn2, nv0, nv1, nv2b, nv3);
            av0 = fmaf(0.9f, av0 - w0 * vc[i][0], w13 * nv0);
            av1 = fmaf(0.9f, av1 - w0 * vc[i][1], w13 * nv1);
            av2 = fmaf(0.9f, av2 - w0 * vc[i][2], w13 * nv2b);
            av3 = fmaf(0.9f, av3 - w0 * vc[i][3], w13 * nv3);
        }
        x4 = make_float4(z0, z1, z2, z3); x2 = zn2;
    }
}

// ---------------------------------------------------------------------------
// KBC: fused MLP.  Block = 128 rows of one iter, 512 threads.
// W1 now read directly from g_w1dup (pre-duplicated packed pairs) with
// one-k prefetch: no splats, no sW1 staging.  smem = 147840 B.
// ---------------------------------------------------------------------------
__global__ __launch_bounds__(512, 1)
void kbc_kernel(float* __restrict__ out,
                const float* __restrict__ b1, const float* __restrict__ W2,
                const float* __restrict__ b2)
{
    extern __shared__ float sm[];
    float* sT  = sm;                   // [128 k][132 r]  transposed t0 tile
    float* sH  = sT + 128 * 132;       // [128 r][132 k2]
    float* sW2 = sH + 128 * 132;       // [24 s][132 k2]  transposed W2 chunk

    const int tid = threadIdx.x;
    const int i  = blockIdx.x >> 7;            // iter 0..3
    const int rb = blockIdx.x & 127;
    const int rowbase = rb * 128;

    {
        const float* src = g_t0 + (i * NROW + rowbase) * 128;
        for (int idx = tid; idx < 128 * 128; idx += 512) {
            int r = idx >> 7, k = idx & 127;
            sT[k * 132 + r] = src[idx];
        }
    }

    const int tx = tid & 31, ty = tid >> 5;
    const int c0 = tx * 4, r0 = ty * 8;
    const int fl = tid & 127, sq6 = (tid >> 7) * 6;

    ull acc6[6] = {0ull, 0ull, 0ull, 0ull, 0ull, 0ull};

    for (int nc = 0; nc < 4; ++nc) {
        __syncthreads();
        for (int idx = tid; idx < 24 * 128; idx += 512) {
            int s = idx >> 7, k2 = idx & 127;
            sW2[s * 132 + k2] = W2[(nc * 128 + k2) * 24 + s];
        }
        __syncthreads();

        // GEMM1: rows r0..r0+7 (4 pairs) x cols c0..c0+3; W1 pairs from gmem
        float4 bb = *(const float4*)&b1[nc * 128 + c0];
        ull bc0 = splat2(bb.x), bc1 = splat2(bb.y), bc2 = splat2(bb.z), bc3 = splat2(bb.w);
        ull hacc[4][4];
#pragma unroll
        for (int rp = 0; rp < 4; ++rp) {
            hacc[rp][0] = bc0; hacc[rp][1] = bc1; hacc[rp][2] = bc2; hacc[rp][3] = bc3;
        }
        const float* wbase = g_w1dup + (nc * 128 + c0) * 2;   // + k*1024
        ull wn0, wn1, wn2, wn3;
        ldg2u(wn0, wn1, wbase);
        ldg2u(wn2, wn3, wbase + 4);
#pragma unroll 2
        for (int k = 0; k < 128; ++k) {
            ull w0 = wn0, w1 = wn1, w2 = wn2, w3 = wn3;
            if (k < 127) {                                   // prefetch next k
                const float* wp = wbase + (k + 1) * 1024;
                ldg2u(wn0, wn1, wp);
                ldg2u(wn2, wn3, wp + 4);
            }
            ull a0, a1, a2, a3;                              // 4 row-pairs (broadcast)
            lds2u(a0, a1, sT + k * 132 + r0);
            lds2u(a2, a3, sT + k * 132 + r0 + 4);
            fma2(hacc[0][0], a0, w0); fma2(hacc[0][1], a0, w1); fma2(hacc[0][2], a0, w2); fma2(hacc[0][3], a0, w3);
            fma2(hacc[1][0], a1, w0); fma2(hacc[1][1], a1, w1); fma2(hacc[1][2], a1, w2); fma2(hacc[1][3], a1, w3);
            fma2(hacc[2][0], a2, w0); fma2(hacc[2][1], a2, w1); fma2(hacc[2][2], a2, w2); fma2(hacc[2][3], a2, w3);
            fma2(hacc[3][0], a3, w0); fma2(hacc[3][1], a3, w1); fma2(hacc[3][2], a3, w2); fma2(hacc[3][3], a3, w3);
        }
#pragma unroll
        for (int rp = 0; rp < 4; ++rp) {
            float lo, hi;
            float* d0 = sH + (r0 + 2 * rp) * 132 + c0;
            float* d1 = d0 + 132;
#pragma unroll
            for (int c = 0; c < 4; ++c) {
                unpack2(hacc[rp][c], lo, hi);
                d0[c] = fmaxf(lo, 0.f);
                d1[c] = fmaxf(hi, 0.f);
            }
        }
        __syncthreads();

        // GEMM2: out[fl][sq6..sq6+5] += h[fl][:] @ W2c  (k2-paired, no splats)
#pragma unroll 4
        for (int k2 = 0; k2 < 128; k2 += 4) {
            ull h01, h23;
            lds2u(h01, h23, sH + fl * 132 + k2);
#pragma unroll
            for (int s = 0; s < 6; ++s) {
                ull wA, wB;
                lds2u(wA, wB, sW2 + (sq6 + s) * 132 + k2);
                fma2(acc6[s], h01, wA);
                fma2(acc6[s], h23, wB);
            }
        }
    }

    const int row_g = rowbase + fl;
    const int b = row_g >> 7;
    const int f = row_g & 127;
#pragma unroll
    for (int s = 0; s < 6; ++s) {
        float lo, hi;
        unpack2(acc6[s], lo, hi);
        int so = sq6 + s;
        out[(b * 96 + i * 24 + so) * 128 + f] = lo + hi + b2[so];
    }
}

// ---------------------------------------------------------------------------
extern "C" void kernel_launch(void* const* d_in, const int* in_sizes, int n_in,
                              void* d_out, int out_size)
{
    const float* trend = (const float*)d_in[0];
    const float* scoar = (const float*)d_in[1];
    const float* sfin  = (const float*)d_in[2];
    const float* resid = (const float*)d_in[3];
    const float* Wt = (const float*)d_in[4];
    const float* bt = (const float*)d_in[5];
    const float* Wc = (const float*)d_in[6];
    const float* bc = (const float*)d_in[7];
    const float* Wf = (const float*)d_in[8];
    const float* bf = (const float*)d_in[9];
    const float* Wr = (const float*)d_in[10];
    const float* br = (const float*)d_in[11];
    const float* alpha = (const float*)d_in[12];
    const float* W1 = (const float*)d_in[13];
    const float* b1 = (const float*)d_in[14];
    const float* W2 = (const float*)d_in[15];
    const float* b2 = (const float*)d_in[16];

    cudaFuncSetAttribute(ka1_kernel, cudaFuncAttributeMaxDynamicSharedMemorySize, 98816);
    cudaFuncSetAttribute(kbc_kernel, cudaFuncAttributeMaxDynamicSharedMemorySize, 147840);

    kprep_kernel<<<256, 256>>>(W1);
    ka1_kernel<<<1920, 256, 98816>>>(trend, scoar, sfin, resid,
                                     Wt, bt, Wc, bc, Wf, bf, Wr, br);
    ka2_kernel<<<2048, 256>>>(alpha);
    kbc_kernel<<<512, 512, 147840>>>((float*)d_out, b1, W2, b2);
}

// round 15
// speedup vs baseline: 1.3737x; 1.3737x over previous
#include <cuda_runtime.h>
#include <math.h>

#define NROW 16384          // B*F rows
#define MTOT 65536          // NPRED * NROW

// Scratch (static device arrays — allocation-free)
__device__ float g_z[NROW * 15 * 128];   // window embeddings z_0..z_14 per row
__device__ float g_zn2[NROW * 15];       // squared norms of z
__device__ float g_t0[MTOT * 128];       // logmap0(z_next) per (iter,row)

// ---------------------------------------------------------------- helpers
__device__ __forceinline__ float wsum(float v) {
#pragma unroll
    for (int o = 16; o; o >>= 1) v += __shfl_xor_sync(0xffffffffu, v, o);
    return v;
}
__device__ __forceinline__ float artanh_c(float x) {
    x = fminf(fmaxf(x, -1.0f + 1e-7f), 1.0f - 1e-7f);
    return 0.5f * logf((1.0f + x) / (1.0f - x));
}
typedef unsigned long long ull;
__device__ __forceinline__ void fma2(ull& c, ull a, ull b) {
    asm("fma.rn.f32x2 %0, %1, %2, %0;" : "+l"(c) : "l"(a), "l"(b));
}
__device__ __forceinline__ ull splat2(float x) {
    ull r; asm("mov.b64 %0, {%1, %1};" : "=l"(r) : "f"(x)); return r;
}
__device__ __forceinline__ void unpack2(ull v, float& lo, float& hi) {
    asm("mov.b64 {%0, %1}, %2;" : "=f"(lo), "=f"(hi) : "l"(v));
}
// 16B shared load delivering two packed f32 pairs (no movs)
__device__ __forceinline__ void lds2u(ull& a, ull& b, const float* p) {
    unsigned sa = (unsigned)__cvta_generic_to_shared(p);
    asm("ld.shared.v2.b64 {%0,%1}, [%2];" : "=l"(a), "=l"(b) : "r"(sa));
}

// logmap(x, y) -> velocity vector (lane holds 4 of 128 dims); serial version
__device__ __forceinline__ void logmap_v(float4 x4, float x2, float4 y4, float y2,
                                         float& v0, float& v1, float& v2, float& v3)
{
    float xy = wsum(x4.x*y4.x + x4.y*y4.y + x4.z*y4.z + x4.w*y4.w);
    float cA = 1.0f - 2.0f*xy + y2;
    float cB = 1.0f - x2;
    float iden = 1.0f / fmaxf(1.0f - 2.0f*xy + x2*y2, 1e-6f);
    float d0 = (cB*y4.x - cA*x4.x)*iden;
    float d1 = (cB*y4.y - cA*x4.y)*iden;
    float d2 = (cB*y4.z - cA*x4.z)*iden;
    float d3 = (cB*y4.w - cA*x4.w)*iden;
    float n2 = wsum(d0*d0 + d1*d1 + d2*d2 + d3*d3);
    float n  = sqrtf(fmaxf(n2, 1e-12f));
    float fac = fmaxf(cB, 1e-6f) * artanh_c(n) / n;
    v0 = fac*d0; v1 = fac*d1; v2 = fac*d2; v3 = fac*d3;
}

// ---------------------------------------------------------------------------
// KA1: embedding GEMM + expmap0.  Block = (b, segment j of window).
// Warp = 16 f rows (8 packed f-pairs), lane = 4 dims. (R10 version — proven)
// ---------------------------------------------------------------------------
__global__ __launch_bounds__(256, 2)
void ka1_kernel(const float* __restrict__ trend, const float* __restrict__ scoar,
                const float* __restrict__ sfin,  const float* __restrict__ resid,
                const float* __restrict__ Wt, const float* __restrict__ bt,
                const float* __restrict__ Wc, const float* __restrict__ bc,
                const float* __restrict__ Wf, const float* __restrict__ bff,
                const float* __restrict__ Wr, const float* __restrict__ br)
{
    extern __shared__ float sm[];
    float* sA    = sm;            // [96 k][128 f]
    float* sW    = sA + 12288;    // [96 k][128 d]
    float* sbias = sW + 12288;    // 128

    const int tid = threadIdx.x;
    const int b = blockIdx.x / 15;
    const int j = blockIdx.x - b * 15;
    const int lbase = b * 720 + 360 + j * 24;

    {
        const float* ptrs[4] = {trend, scoar, sfin, resid};
        const float* wptr[4] = {Wt, Wc, Wf, Wr};
#pragma unroll
        for (int st = 0; st < 4; ++st) {
            const float* p = ptrs[st] + lbase * 128;
            for (int idx = tid; idx < 3072; idx += 256) sA[st * 3072 + idx] = p[idx];
            const float* wp = wptr[st];
            for (int idx = tid; idx < 3072; idx += 256) sW[st * 3072 + idx] = wp[idx];
        }
    }
    if (tid < 128) sbias[tid] = bt[tid] + bc[tid] + bff[tid] + br[tid];
    __syncthreads();

    const int w = tid >> 5, lane = tid & 31;
    const int fb = w * 16;

    const float4 bias4 = ((const float4*)sbias)[lane];
    ull bini[4] = { splat2(bias4.x), splat2(bias4.y), splat2(bias4.z), splat2(bias4.w) };
    ull acc[8][4];
#pragma unroll
    for (int p = 0; p < 8; ++p)
#pragma unroll
        for (int d = 0; d < 4; ++d) acc[p][d] = bini[d];

    const float4* sW4 = (const float4*)sW;
    float4 wvp = sW4[lane];                       // prefetch k=0 weights
#pragma unroll 2
    for (int k = 0; k < 96; ++k) {
        float4 wv = wvp;
        if (k < 95) wvp = sW4[(k + 1) * 32 + lane];   // prefetch next k
        ull wd0 = splat2(wv.x), wd1 = splat2(wv.y), wd2 = splat2(wv.z), wd3 = splat2(wv.w);
        const float* ab = sA + k * 128 + fb;      // f-contiguous (broadcast)
        ull a0, a1, a2, a3, a4, a5, a6, a7;
        lds2u(a0, a1, ab);
        lds2u(a2, a3, ab + 4);
        lds2u(a4, a5, ab + 8);
        lds2u(a6, a7, ab + 12);
        fma2(acc[0][0], a0, wd0); fma2(acc[0][1], a0, wd1); fma2(acc[0][2], a0, wd2); fma2(acc[0][3], a0, wd3);
        fma2(acc[1][0], a1, wd0); fma2(acc[1][1], a1, wd1); fma2(acc[1][2], a1, wd2); fma2(acc[1][3], a1, wd3);
        fma2(acc[2][0], a2, wd0); fma2(acc[2][1], a2, wd1); fma2(acc[2][2], a2, wd2); fma2(acc[2][3], a2, wd3);
        fma2(acc[3][0], a3, wd0); fma2(acc[3][1], a3, wd1); fma2(acc[3][2], a3, wd2); fma2(acc[3][3], a3, wd3);
        fma2(acc[4][0], a4, wd0); fma2(acc[4][1], a4, wd1); fma2(acc[4][2], a4, wd2); fma2(acc[4][3], a4, wd3);
        fma2(acc[5][0], a5, wd0); fma2(acc[5][1], a5, wd1); fma2(acc[5][2], a5, wd2); fma2(acc[5][3], a5, wd3);
        fma2(acc[6][0], a6, wd0); fma2(acc[6][1], a6, wd1); fma2(acc[6][2], a6, wd2); fma2(acc[6][3], a6, wd3);
        fma2(acc[7][0], a7, wd0); fma2(acc[7][1], a7, wd1); fma2(acc[7][2], a7, wd2); fma2(acc[7][3], a7, wd3);
    }

    // ---- epilogue: batched reductions over 16 rows ----
    float pn[16];
#pragma unroll
    for (int p = 0; p < 8; ++p) {
        float lo0, hi0, lo1, hi1, lo2, hi2, lo3, hi3;
        unpack2(acc[p][0], lo0, hi0);
        unpack2(acc[p][1], lo1, hi1);
        unpack2(acc[p][2], lo2, hi2);
        unpack2(acc[p][3], lo3, hi3);
        pn[2*p]   = lo0*lo0 + lo1*lo1 + lo2*lo2 + lo3*lo3;
        pn[2*p+1] = hi0*hi0 + hi1*hi1 + hi2*hi2 + hi3*hi3;
    }
#pragma unroll
    for (int o = 16; o; o >>= 1)
#pragma unroll
        for (int r = 0; r < 16; ++r)
            pn[r] += __shfl_xor_sync(0xffffffffu, pn[r], o);

    const int rowb = b * 128 + fb;
#pragma unroll
    for (int p = 0; p < 8; ++p) {
        float v[2][4];
        unpack2(acc[p][0], v[0][0], v[1][0]);
        unpack2(acc[p][1], v[0][1], v[1][1]);
        unpack2(acc[p][2], v[0][2], v[1][2]);
        unpack2(acc[p][3], v[0][3], v[1][3]);
#pragma unroll
        for (int e = 0; e < 2; ++e) {
            float n2 = pn[2*p + e];
            float n  = sqrtf(fmaxf(n2, 1e-12f));
            float t  = tanhf(n);
            float tc = fminf(t, 0.99999f);     // |z| = tanh(n); project clamps it
            float scl = tc / n;
            int row = rowb + 2 * p + e;
            ((float4*)(g_z + (row * 15 + j) * 128))[lane] =
                make_float4(scl*v[e][0], scl*v[e][1], scl*v[e][2], scl*v[e][3]);
            if (lane == 0) g_zn2[row * 15 + j] = tc * tc;
        }
    }
}

// ---------------------------------------------------------------------------
// KA2: 4-step recurrence.  Warp = one (b,f) row; lane = 4 dims. (unchanged)
// ---------------------------------------------------------------------------
__global__ __launch_bounds__(256)
void ka2_kernel(const float* __restrict__ alphap)
{
    const int w = threadIdx.x >> 5, lane = threadIdx.x & 31;
    const int row = blockIdx.x * 8 + w;
    const float alpha = alphap[0];

    float S = 0.0f, p = 1.0f;
#pragma unroll
    for (int e = 0; e < 14; ++e) { S += p; p *= 0.9f; }
    const float w13 = 1.0f / S;
    float w0 = w13;
#pragma unroll
    for (int e = 0; e < 13; ++e) w0 *= 0.9f;
    const float inv09 = 1.0f / 0.9f;

    const float* zp = g_z   + row * 15 * 128;
    const float* np = g_zn2 + row * 15;

    float4 z[15]; float zn[15];
#pragma unroll
    for (int jj = 0; jj < 15; ++jj) {
        z[jj]  = ((const float4*)(zp + jj * 128))[lane];
        zn[jj] = __ldg(np + jj);
    }

    float px[14];
#pragma unroll
    for (int jj = 0; jj < 14; ++jj)
        px[jj] = z[jj].x*z[jj+1].x + z[jj].y*z[jj+1].y +
                 z[jj].z*z[jj+1].z + z[jj].w*z[jj+1].w;
#pragma unroll
    for (int o = 16; o; o >>= 1)
#pragma unroll
        for (int jj = 0; jj < 14; ++jj)
            px[jj] += __shfl_xor_sync(0xffffffffu, px[jj], o);

    float d[14][4]; float pn[14];
#pragma unroll
    for (int jj = 0; jj < 14; ++jj) {
        float x2 = zn[jj], y2 = zn[jj+1], xy = px[jj];
        float cA = 1.0f - 2.0f*xy + y2;
        float cB = 1.0f - x2;
        float iden = 1.0f / fmaxf(1.0f - 2.0f*xy + x2*y2, 1e-6f);
        d[jj][0] = (cB*z[jj+1].x - cA*z[jj].x)*iden;
        d[jj][1] = (cB*z[jj+1].y - cA*z[jj].y)*iden;
        d[jj][2] = (cB*z[jj+1].z - cA*z[jj].z)*iden;
        d[jj][3] = (cB*z[jj+1].w - cA*z[jj].w)*iden;
        pn[jj] = d[jj][0]*d[jj][0] + d[jj][1]*d[jj][1] +
                 d[jj][2]*d[jj][2] + d[jj][3]*d[jj][3];
    }
#pragma unroll
    for (int o = 16; o; o >>= 1)
#pragma unroll
        for (int jj = 0; jj < 14; ++jj)
            pn[jj] += __shfl_xor_sync(0xffffffffu, pn[jj], o);

    float av0 = 0.f, av1 = 0.f, av2 = 0.f, av3 = 0.f;
    float vc[3][4];
    float wcur = w0;
#pragma unroll
    for (int jj = 0; jj < 14; ++jj) {
        float n = sqrtf(fmaxf(pn[jj], 1e-12f));
        float fac = fmaxf(1.0f - zn[jj], 1e-6f) * artanh_c(n) / n;
        float v0 = fac*d[jj][0], v1 = fac*d[jj][1], v2 = fac*d[jj][2], v3 = fac*d[jj][3];
        if (jj < 3) { vc[jj][0] = v0; vc[jj][1] = v1; vc[jj][2] = v2; vc[jj][3] = v3; }
        av0 = fmaf(wcur, v0, av0); av1 = fmaf(wcur, v1, av1);
        av2 = fmaf(wcur, v2, av2); av3 = fmaf(wcur, v3, av3);
        wcur *= inv09;
    }

    float4 x4 = z[14];
    float  x2 = zn[14];

#pragma unroll
    for (int i = 0; i < 4; ++i) {
        float v0 = alpha * av0, v1 = alpha * av1, v2 = alpha * av2, v3 = alpha * av3;
        float nv2 = wsum(v0*v0 + v1*v1 + v2*v2 + v3*v3);
        float nv  = sqrtf(fmaxf(nv2, 1e-12f));
        float om  = fmaxf(1.0f - x2, 1e-6f);
        float sscl = tanhf(nv / om) / nv;
        float e0 = sscl*v0, e1 = sscl*v1, e2 = sscl*v2, e3 = sscl*v3;
        float xy = wsum(x4.x*e0 + x4.y*e1 + x4.z*e2 + x4.w*e3);
        float s2 = wsum(e0*e0 + e1*e1 + e2*e2 + e3*e3);
        float cA = 1.0f + 2.0f*xy + s2;
        float cB = 1.0f - x2;
        float iden = 1.0f / fmaxf(1.0f + 2.0f*xy + x2*s2, 1e-6f);
        float z0 = (cA*x4.x + cB*e0)*iden;
        float z1 = (cA*x4.y + cB*e1)*iden;
        float z2 = (cA*x4.z + cB*e2)*iden;
        float z3 = (cA*x4.w + cB*e3)*iden;
        float zn2 = wsum(z0*z0 + z1*z1 + z2*z2 + z3*z3);
        float znn = sqrtf(fmaxf(zn2, 1e-12f));
        if (znn > 0.99999f) {
            float ps = 0.99999f / znn;
            z0 *= ps; z1 *= ps; z2 *= ps; z3 *= ps;
            zn2 *= ps * ps;
        }
        float tn = sqrtf(fmaxf(zn2, 1e-12f));
        float tf = artanh_c(tn) / tn;
        ((float4*)(g_t0 + (i * NROW + row) * 128))[lane] =
            make_float4(tf*z0, tf*z1, tf*z2, tf*z3);

        if (i < 3) {
            float4 zn4 = make_float4(z0, z1, z2, z3);
            float nv0, nv1, nv2b, nv3;
            logmap_v(x4, x2, zn4, zn2, nv0, nv1, nv2b, nv3);
            av0 = fmaf(0.9f, av0 - w0 * vc[i][0], w13 * nv0);
            av1 = fmaf(0.9f, av1 - w0 * vc[i][1], w13 * nv1);
            av2 = fmaf(0.9f, av2 - w0 * vc[i][2], w13 * nv2b);
            av3 = fmaf(0.9f, av3 - w0 * vc[i][3], w13 * nv3);
        }
        x4 = make_float4(z0, z1, z2, z3); x2 = zn2;
    }
}

// ---------------------------------------------------------------------------
// KBC: fused MLP.  64-row tiles, 256 threads, 8 chunks of 64 W1-cols.
// smem = 91520 B -> 2 blocks/SM (16 warps).  grid = 1024 -> ~1% tail loss.
// GEMM1 micro-tile: 2 row-pairs x 4 cols (8 FFMA2/k); GEMM2 k2-paired.
// ---------------------------------------------------------------------------
__global__ __launch_bounds__(256, 2)
void kbc_kernel(float* __restrict__ out, const float* __restrict__ W1,
                const float* __restrict__ b1, const float* __restrict__ W2,
                const float* __restrict__ b2)
{
    extern __shared__ float sm[];
    float* sT  = sm;                   // [128 k][68]   transposed t0 tile (64 rows)
    float* sW1 = sT + 128 * 68;        // [128 k][64 c]
    float* sH  = sW1 + 128 * 64;       // [64 r][68]    relu activations (64-col chunk)
    float* sW2 = sH + 64 * 68;         // [24 s][68]    transposed W2 chunk

    const int tid = threadIdx.x;
    const int i  = blockIdx.x >> 8;            // iter 0..3
    const int rb = blockIdx.x & 255;           // tile 0..255
    const int rowbase = rb * 64;

    // stage t0 tile transposed: sT[k][r]  (coalesced LDG, 4-way STS conflicts ok)
    {
        const float* src = g_t0 + (i * NROW + rowbase) * 128;
        for (int idx = tid; idx < 64 * 128; idx += 256) {
            int r = idx >> 7, k = idx & 127;
            sT[k * 68 + r] = src[idx];
        }
    }

    const int tx = tid & 15, ty = tid >> 4;    // GEMM1: 16 col-threads x 16 row-groups
    const int c0 = tx * 4, r0 = ty * 4;        // 4 cols, 2 row-pairs per thread
    const int fl = tid & 63, sq6 = (tid >> 6) * 6;   // GEMM2: 64 rows x 4 s-groups

    ull acc6[6] = {0ull, 0ull, 0ull, 0ull, 0ull, 0ull};

    for (int nc = 0; nc < 8; ++nc) {
        __syncthreads();   // prev chunk fully consumed
        // stage W1 chunk [128 k][64 c] vectorized
        for (int idx = tid; idx < 128 * 16; idx += 256) {
            int k = idx >> 4, cq = idx & 15;
            *(float4*)&sW1[k * 64 + cq * 4] =
                *(const float4*)&W1[k * 512 + nc * 64 + cq * 4];
        }
        // stage W2 chunk transposed [24 s][64 k2]
        for (int idx = tid; idx < 24 * 64; idx += 256) {
            int s = idx >> 6, k2 = idx & 63;
            sW2[s * 68 + k2] = W2[(nc * 64 + k2) * 24 + s];
        }
        __syncthreads();

        // GEMM1: h[r0..r0+3][c0..c0+3] = t0 @ W1c + b1, relu -> sH
        float4 bb = *(const float4*)&b1[nc * 64 + c0];
        ull hacc[2][4];
        hacc[0][0] = splat2(bb.x); hacc[0][1] = splat2(bb.y);
        hacc[0][2] = splat2(bb.z); hacc[0][3] = splat2(bb.w);
        hacc[1][0] = hacc[0][0]; hacc[1][1] = hacc[0][1];
        hacc[1][2] = hacc[0][2]; hacc[1][3] = hacc[0][3];
#pragma unroll 4
        for (int k = 0; k < 128; ++k) {
            ull a0, a1;                                      // 2 row-pairs (broadcast)
            lds2u(a0, a1, sT + k * 68 + r0);
            float4 wv = *(const float4*)&sW1[k * 64 + c0];   // per-lane
            ull w0 = splat2(wv.x), w1 = splat2(wv.y), w2 = splat2(wv.z), w3 = splat2(wv.w);
            fma2(hacc[0][0], a0, w0); fma2(hacc[0][1], a0, w1);
            fma2(hacc[0][2], a0, w2); fma2(hacc[0][3], a0, w3);
            fma2(hacc[1][0], a1, w0); fma2(hacc[1][1], a1, w1);
            fma2(hacc[1][2], a1, w2); fma2(hacc[1][3], a1, w3);
        }
#pragma unroll
        for (int rp = 0; rp < 2; ++rp) {
            float lo, hi;
            float* d0 = sH + (r0 + 2 * rp) * 68 + c0;
            float* d1 = d0 + 68;
#pragma unroll
            for (int c = 0; c < 4; ++c) {
                unpack2(hacc[rp][c], lo, hi);
                d0[c] = fmaxf(lo, 0.f);
                d1[c] = fmaxf(hi, 0.f);
            }
        }
        __syncthreads();

        // GEMM2: out[fl][sq6..sq6+5] += h[fl][:] @ W2c  (k2-paired, no splats)
#pragma unroll 4
        for (int k2 = 0; k2 < 64; k2 += 4) {
            ull h01, h23;
            lds2u(h01, h23, sH + fl * 68 + k2);              // conflict-free
#pragma unroll
            for (int s = 0; s < 6; ++s) {
                ull wA, wB;
                lds2u(wA, wB, sW2 + (sq6 + s) * 68 + k2);    // warp-broadcast
                fma2(acc6[s], h01, wA);
                fma2(acc6[s], h23, wB);
            }
        }
    }

    // write predictions: out[(b*96 + i*24 + s)*128 + f]
    const int row_g = rowbase + fl;
    const int b = row_g >> 7;
    const int f = row_g & 127;
#pragma unroll
    for (int s = 0; s < 6; ++s) {
        float lo, hi;
        unpack2(acc6[s], lo, hi);
        int so = sq6 + s;
        out[(b * 96 + i * 24 + so) * 128 + f] = lo + hi + b2[so];
    }
}

// ---------------------------------------------------------------------------
extern "C" void kernel_launch(void* const* d_in, const int* in_sizes, int n_in,
                              void* d_out, int out_size)
{
    const float* trend = (const float*)d_in[0];
    const float* scoar = (const float*)d_in[1];
    const float* sfin  = (const float*)d_in[2];
    const float* resid = (const float*)d_in[3];
    const float* Wt = (const float*)d_in[4];
    const float* bt = (const float*)d_in[5];
    const float* Wc = (const float*)d_in[6];
    const float* bc = (const float*)d_in[7];
    const float* Wf = (const float*)d_in[8];
    const float* bf = (const float*)d_in[9];
    const float* Wr = (const float*)d_in[10];
    const float* br = (const float*)d_in[11];
    const float* alpha = (const float*)d_in[12];
    const float* W1 = (const float*)d_in[13];
    const float* b1 = (const float*)d_in[14];
    const float* W2 = (const float*)d_in[15];
    const float* b2 = (const float*)d_in[16];

    cudaFuncSetAttribute(ka1_kernel, cudaFuncAttributeMaxDynamicSharedMemorySize, 98816);
    cudaFuncSetAttribute(kbc_kernel, cudaFuncAttributeMaxDynamicSharedMemorySize, 91520);

    ka1_kernel<<<1920, 256, 98816>>>(trend, scoar, sfin, resid,
                                     Wt, bt, Wc, bc, Wf, bf, Wr, br);
    ka2_kernel<<<2048, 256>>>(alpha);
    kbc_kernel<<<1024, 256, 91520>>>((float*)d_out, W1, b1, W2, b2);
}